// round 1
// baseline (speedup 1.0000x reference)
#include <cuda_runtime.h>

// Problem constants (fixed shapes per reference)
#define CONCEPTS 128
#define MM 14          // nb_mod_max + 2
#define DC 128         // concept dim
#define DIN 3

// Per-concept Gram matrix G = W[c] @ W[c]^T (3x3 symmetric -> 6 unique values)
// __device__ global scratch (no allocations allowed in kernel_launch).
__device__ float g_G[CONCEPTS * 6];

// ---------------------------------------------------------------------------
// Kernel 1: precompute G[c] = W[c] W[c]^T for all 128 concepts.
// One warp per concept; lane l owns 4 channels.
// ---------------------------------------------------------------------------
__global__ void gmat_kernel(const float* __restrict__ W) {
    int c = blockIdx.x;
    int lane = threadIdx.x;
    const float4* w = reinterpret_cast<const float4*>(W + (size_t)c * DIN * DC);
    float4 a = w[lane];          // row d=0, channels 4l..4l+3
    float4 b = w[32 + lane];     // row d=1
    float4 d = w[64 + lane];     // row d=2
    float s[6];
    s[0] = a.x*a.x + a.y*a.y + a.z*a.z + a.w*a.w;  // G00
    s[1] = a.x*b.x + a.y*b.y + a.z*b.z + a.w*b.w;  // G01
    s[2] = a.x*d.x + a.y*d.y + a.z*d.z + a.w*d.w;  // G02
    s[3] = b.x*b.x + b.y*b.y + b.z*b.z + b.w*b.w;  // G11
    s[4] = b.x*d.x + b.y*d.y + b.z*d.z + b.w*d.w;  // G12
    s[5] = d.x*d.x + d.y*d.y + d.z*d.z + d.w*d.w;  // G22
    #pragma unroll
    for (int off = 16; off; off >>= 1) {
        #pragma unroll
        for (int k = 0; k < 6; k++)
            s[k] += __shfl_xor_sync(0xffffffffu, s[k], off);
    }
    if (lane == 0) {
        #pragma unroll
        for (int k = 0; k < 6; k++) g_G[c * 6 + k] = s[k];
    }
}

// ---------------------------------------------------------------------------
// Kernel 2: one warp per batch row.
//   v = W[c]^T u            (3 length-128 dots, warp-parallel + butterfly)
//   score[m] = e_m^T G e_m - 2 e_m . v + mask[item][m]
//   argmin (first-index tie-break) -> response
// ---------------------------------------------------------------------------
__global__ void impact_kernel(
    const int*   __restrict__ user_ids,
    const int*   __restrict__ item_ids,
    const int*   __restrict__ concept_ids,
    const float* __restrict__ uemb,     // (USER_N, 128)
    const float* __restrict__ irw,      // (ITEM_N*14, 3)
    const float* __restrict__ W,        // (128, 3, 128)
    const float* __restrict__ maskt,    // (ITEM_N, 14)
    const int*   __restrict__ nbmod,    // (ITEM_N,)
    float*       __restrict__ out,
    int nrows)
{
    int warp = (int)((blockIdx.x * blockDim.x + threadIdx.x) >> 5);
    int lane = threadIdx.x & 31;
    if (warp >= nrows) return;

    int u  = user_ids[warp];
    int it = item_ids[warp];
    int c  = concept_ids[warp];

    // Coalesced float4 loads: lane l owns channels 4l..4l+3
    const float4* uv = reinterpret_cast<const float4*>(uemb + (size_t)u * DC);
    const float4* wv = reinterpret_cast<const float4*>(W + (size_t)c * DIN * DC);
    float4 uu = uv[lane];
    float4 w0 = wv[lane];
    float4 w1 = wv[32 + lane];
    float4 w2 = wv[64 + lane];

    float v0 = uu.x*w0.x + uu.y*w0.y + uu.z*w0.z + uu.w*w0.w;
    float v1 = uu.x*w1.x + uu.y*w1.y + uu.z*w1.z + uu.w*w1.w;
    float v2 = uu.x*w2.x + uu.y*w2.y + uu.z*w2.z + uu.w*w2.w;
    #pragma unroll
    for (int off = 16; off; off >>= 1) {
        v0 += __shfl_xor_sync(0xffffffffu, v0, off);
        v1 += __shfl_xor_sync(0xffffffffu, v1, off);
        v2 += __shfl_xor_sync(0xffffffffu, v2, off);
    }
    // all lanes now hold the full v

    float score = __int_as_float(0x7f800000);  // +inf for lanes >= MM
    if (lane < MM) {
        const float* e = irw + ((size_t)it * MM + lane) * DIN;
        float e0 = e[0], e1 = e[1], e2 = e[2];
        const float* G = g_G + c * 6;
        float q = e0*e0*G[0] + e1*e1*G[3] + e2*e2*G[5]
                + 2.0f*(e0*e1*G[1] + e0*e2*G[2] + e1*e2*G[4]);
        score = q - 2.0f*(e0*v0 + e1*v1 + e2*v2)
              + maskt[(size_t)it * MM + lane];
    }

    // Lexicographic (value, index) argmin — matches jnp.argmin first-min rule.
    int best = lane;
    #pragma unroll
    for (int off = 16; off; off >>= 1) {
        float ov = __shfl_xor_sync(0xffffffffu, score, off);
        int   oi = __shfl_xor_sync(0xffffffffu, best,  off);
        if (ov < score || (ov == score && oi < best)) { score = ov; best = oi; }
    }

    if (lane == 0) {
        float nb = (float)nbmod[it];
        out[warp] = ((float)best - 1.0f) / (nb - 1.0f) + 1.0f;
    }
}

extern "C" void kernel_launch(void* const* d_in, const int* in_sizes, int n_in,
                              void* d_out, int out_size) {
    const int*   user_ids    = (const int*)  d_in[0];
    const int*   item_ids    = (const int*)  d_in[1];
    const int*   concept_ids = (const int*)  d_in[2];
    const float* uemb        = (const float*)d_in[3];
    const float* irw         = (const float*)d_in[4];
    const float* W           = (const float*)d_in[5];
    const float* maskt       = (const float*)d_in[6];
    const int*   nbmod       = (const int*)  d_in[7];
    float* out = (float*)d_out;
    int nrows = in_sizes[0];

    gmat_kernel<<<CONCEPTS, 32>>>(W);

    const int warpsPerBlock = 8;  // 256 threads
    int blocks = (nrows + warpsPerBlock - 1) / warpsPerBlock;
    impact_kernel<<<blocks, warpsPerBlock * 32>>>(
        user_ids, item_ids, concept_ids, uemb, irw, W, maskt, nbmod, out, nrows);
}